// round 4
// baseline (speedup 1.0000x reference)
#include <cuda_runtime.h>
#include <cstdint>

#define HDIM 2048
#define NTOK 8192          // B*S
#define NTHREADS 512
#define EPSV 1e-6f
#define ROWB (HDIM * 4)    // bytes per staged row

__device__ __forceinline__ void cp16(uint32_t saddr, const void* g) {
    asm volatile("cp.async.cg.shared.global [%0], [%1], 16;" :: "r"(saddr), "l"(g));
}
__device__ __forceinline__ void stcs4(float* p, float4 v) {
    asm volatile("st.global.cs.v4.f32 [%0], {%1,%2,%3,%4};"
                 :: "l"(p), "f"(v.x), "f"(v.y), "f"(v.z), "f"(v.w));
}
__device__ __forceinline__ float tanh_fast(float x) {
    float y; asm("tanh.approx.f32 %0, %1;" : "=f"(y) : "f"(x)); return y;
}
__device__ __forceinline__ float dot4(float4 a, float4 b) {
    return a.x*b.x + a.y*b.y + a.z*b.z + a.w*b.w;
}

__global__ __launch_bounds__(NTHREADS, 3)
void altup_cp_kernel(const float* __restrict__ hs,     // [4, NTOK, H]
                     const float* __restrict__ act,    // [NTOK, H]
                     const float* __restrict__ w,      // [H]
                     const float* __restrict__ rw,     // [4, H]
                     const float* __restrict__ pw,     // [16, 4]
                     const float* __restrict__ cw,     // [4, 4]
                     const float* __restrict__ oscale, // [H]
                     float* __restrict__ out)          // [4, NTOK, H]
{
    const int t   = blockIdx.x;
    const int tid = threadIdx.x;
    const int h4  = tid * 4;

    __shared__ float stage[5][HDIM];   // rows: x0, act, x1, x2, x3
    __shared__ float red[16][10];
    __shared__ float fin[10];

    const uint32_t sbase = (uint32_t)__cvta_generic_to_shared(&stage[0][0]);
    const uint32_t soff  = (uint32_t)(tid * 16);

    // ---- async stage-in: group A = {x0, act}, group B = {x1, x2, x3} ----
    cp16(sbase + 0*ROWB + soff, hs  + (size_t)t * HDIM + h4);
    cp16(sbase + 1*ROWB + soff, act + (size_t)t * HDIM + h4);
    asm volatile("cp.async.commit_group;" ::: "memory");
    cp16(sbase + 2*ROWB + soff, hs + ((size_t)1*NTOK + t)*HDIM + h4);
    cp16(sbase + 3*ROWB + soff, hs + ((size_t)2*NTOK + t)*HDIM + h4);
    cp16(sbase + 4*ROWB + soff, hs + ((size_t)3*NTOK + t)*HDIM + h4);
    asm volatile("cp.async.commit_group;" ::: "memory");

    // ---- wait for x0/act (group B may remain in flight) ----
    asm volatile("cp.async.wait_group 1;" ::: "memory");

    float p[10];
    {
        float4 x0 = *(const float4*)&stage[0][h4];
        float4 av = *(const float4*)&stage[1][h4];
        float4 wv = __ldg((const float4*)(w + h4));
        float4 xw = make_float4(x0.x*wv.x, x0.y*wv.y, x0.z*wv.z, x0.w*wv.w);
        float4 aw = make_float4(av.x*wv.x, av.y*wv.y, av.z*wv.z, av.w*wv.w);
        p[0] = dot4(x0, x0);
        p[5] = dot4(av, av);
        // weights in two halves to bound register peak
        {
            float4 r0 = __ldg((const float4*)(rw + 0*HDIM + h4));
            float4 r1 = __ldg((const float4*)(rw + 1*HDIM + h4));
            p[1] = dot4(xw, r0);  p[2] = dot4(xw, r1);
            p[6] = dot4(aw, r0);  p[7] = dot4(aw, r1);
        }
        {
            float4 r2 = __ldg((const float4*)(rw + 2*HDIM + h4));
            float4 r3 = __ldg((const float4*)(rw + 3*HDIM + h4));
            p[3] = dot4(xw, r2);  p[4] = dot4(xw, r3);
            p[8] = dot4(aw, r2);  p[9] = dot4(aw, r3);
        }
    }

    // ---- block reduce 10 values ----
    #pragma unroll
    for (int k = 0; k < 10; k++) {
        #pragma unroll
        for (int o = 16; o > 0; o >>= 1)
            p[k] += __shfl_xor_sync(0xffffffffu, p[k], o);
    }
    const int warp = tid >> 5, lane = tid & 31;
    if (lane == 0) {
        #pragma unroll
        for (int k = 0; k < 10; k++) red[warp][k] = p[k];
    }
    __syncthreads();
    if (tid < 10) {
        float s = 0.f;
        #pragma unroll
        for (int wi = 0; wi < 16; wi++) s += red[wi][tid];
        fin[tid] = s;
    }
    __syncthreads();

    // ---- per-token coefficient math (redundant across threads) ----
    const float inv_h = 1.0f / (float)HDIM;
    float g0 = rsqrtf(fin[0] * inv_h + EPSV) * inv_h;
    float g1 = rsqrtf(fin[5] * inv_h + EPSV) * inv_h;
    float m0[4], cc[4];
    #pragma unroll
    for (int n = 0; n < 4; n++) m0[n] = tanh_fast(fin[1 + n] * g0);
    #pragma unroll
    for (int n = 0; n < 4; n++) {
        float mv = tanh_fast(fin[6 + n] * g1);
        cc[0] = (n == 0) ? 1.f + mv * __ldg(&cw[0*4])     : fmaf(mv, __ldg(&cw[0*4 + n]), cc[0]);
        cc[1] = (n == 0) ? 1.f + mv * __ldg(&cw[1*4])     : fmaf(mv, __ldg(&cw[1*4 + n]), cc[1]);
        cc[2] = (n == 0) ? 1.f + mv * __ldg(&cw[2*4])     : fmaf(mv, __ldg(&cw[2*4 + n]), cc[2]);
        cc[3] = (n == 0) ? 1.f + mv * __ldg(&cw[3*4])     : fmaf(mv, __ldg(&cw[3*4 + n]), cc[3]);
    }

    // ---- make sure x1..x3 staged ----
    asm volatile("cp.async.wait_group 0;" ::: "memory");

    float4 xv[4];
    xv[0] = *(const float4*)&stage[0][h4];
    xv[1] = *(const float4*)&stage[2][h4];
    xv[2] = *(const float4*)&stage[3][h4];
    xv[3] = *(const float4*)&stage[4][h4];
    float4 av = *(const float4*)&stage[1][h4];
    float4 sv = __ldg((const float4*)(oscale + h4));

    float xc[4][4];
    #pragma unroll
    for (int i = 0; i < 4; i++) {
        xc[i][0]=xv[i].x; xc[i][1]=xv[i].y; xc[i][2]=xv[i].z; xc[i][3]=xv[i].w;
    }
    const float ac[4] = {av.x, av.y, av.z, av.w};
    const float sc[4] = {sv.x, sv.y, sv.z, sv.w};

    // pred rows computed with c built row-by-row to bound register peak
    float pr[4][4];   // pred[j][comp]
    #pragma unroll
    for (int j = 0; j < 4; j++) {
        float cr[4];
        #pragma unroll
        for (int i = 0; i < 4; i++) {
            float s = 0.f;
            #pragma unroll
            for (int n = 0; n < 4; n++) s += m0[n] * __ldg(&pw[(j*4 + i)*4 + n]);
            cr[i] = s;
        }
        #pragma unroll
        for (int comp = 0; comp < 4; comp++) {
            float s = xc[j][comp];
            #pragma unroll
            for (int i = 0; i < 4; i++) s = fmaf(cr[i], xc[i][comp], s);
            pr[j][comp] = s;
        }
    }

    #pragma unroll
    for (int n = 0; n < 4; n++) {
        float4 o4;
        float* op = &o4.x;
        #pragma unroll
        for (int comp = 0; comp < 4; comp++) {
            float innov = ac[comp] - pr[0][comp];
            op[comp] = (pr[n][comp] + innov * cc[n]) * sc[comp];
        }
        stcs4(out + ((size_t)n*NTOK + t)*HDIM + h4, o4);
    }
}

extern "C" void kernel_launch(void* const* d_in, const int* in_sizes, int n_in,
                              void* d_out, int out_size)
{
    const float* hs     = (const float*)d_in[0];
    const float* act    = (const float*)d_in[1];
    const float* w      = (const float*)d_in[2];
    const float* rw     = (const float*)d_in[3];
    const float* pw     = (const float*)d_in[4];
    const float* cw     = (const float*)d_in[5];
    const float* oscale = (const float*)d_in[6];
    float* out = (float*)d_out;

    altup_cp_kernel<<<NTOK, NTHREADS>>>(hs, act, w, rw, pw, cw, oscale, out);
}

// round 5
// speedup vs baseline: 1.1541x; 1.1541x over previous
#include <cuda_runtime.h>
#include <cstdint>

#define HDIM 2048
#define NTOK 8192          // B*S
#define NTHREADS 512
#define NCTAS 304          // 152 SMs * 2 resident CTAs
#define EPSV 1e-6f

__device__ float g_wr[4 * HDIM];   // fused router weights: w * rw[n]

__device__ __forceinline__ float4 ldcs4(const float* p) {
    float4 v;
    asm volatile("ld.global.cs.v4.f32 {%0,%1,%2,%3}, [%4];"
                 : "=f"(v.x), "=f"(v.y), "=f"(v.z), "=f"(v.w) : "l"(p));
    return v;
}
__device__ __forceinline__ void stcs4(float* p, float4 v) {
    asm volatile("st.global.cs.v4.f32 [%0], {%1,%2,%3,%4};"
                 :: "l"(p), "f"(v.x), "f"(v.y), "f"(v.z), "f"(v.w));
}
__device__ __forceinline__ float tanh_fast(float x) {
    float y; asm("tanh.approx.f32 %0, %1;" : "=f"(y) : "f"(x)); return y;
}
__device__ __forceinline__ float dot4(float4 a, float4 b) {
    return a.x*b.x + a.y*b.y + a.z*b.z + a.w*b.w;
}

__global__ void fuse_weights_kernel(const float* __restrict__ w,
                                    const float* __restrict__ rw)
{
    int i = blockIdx.x * blockDim.x + threadIdx.x;   // 0 .. 4*HDIM-1
    if (i < 4 * HDIM) g_wr[i] = w[i & (HDIM - 1)] * rw[i];
}

__global__ __launch_bounds__(NTHREADS, 2)
void altup_persist_kernel(const float* __restrict__ hs,     // [4, NTOK, H]
                          const float* __restrict__ act,    // [NTOK, H]
                          const float* __restrict__ pw,     // [16, 4]
                          const float* __restrict__ cw,     // [4, 4]
                          const float* __restrict__ oscale, // [H]
                          float* __restrict__ out)          // [4, NTOK, H]
{
    const int tid = threadIdx.x;
    const int h4  = tid * 4;

    __shared__ float red[16][10];
    __shared__ float fin[10];

    // ---- persistent per-CTA state: fused weights + output scale ----
    const float4 q0 = *(const float4*)(g_wr + 0*HDIM + h4);
    const float4 q1 = *(const float4*)(g_wr + 1*HDIM + h4);
    const float4 q2 = *(const float4*)(g_wr + 2*HDIM + h4);
    const float4 q3 = *(const float4*)(g_wr + 3*HDIM + h4);
    const float4 sv = *(const float4*)(oscale + h4);

    const int warp = tid >> 5, lane = tid & 31;

    for (int t = blockIdx.x; t < NTOK; t += NCTAS) {
        // ---- phase 1: reduction streams ----
        float4 x0 = ldcs4(hs  + (size_t)t * HDIM + h4);
        float4 av = ldcs4(act + (size_t)t * HDIM + h4);

        float p[10];
        p[0] = dot4(x0, x0);
        p[1] = dot4(x0, q0);  p[2] = dot4(x0, q1);
        p[3] = dot4(x0, q2);  p[4] = dot4(x0, q3);
        p[5] = dot4(av, av);
        p[6] = dot4(av, q0);  p[7] = dot4(av, q1);
        p[8] = dot4(av, q2);  p[9] = dot4(av, q3);

        // ---- prefetch phase-2 streams before the reduce (pinned order) ----
        float4 x1 = ldcs4(hs + ((size_t)1*NTOK + t)*HDIM + h4);
        float4 x2 = ldcs4(hs + ((size_t)2*NTOK + t)*HDIM + h4);
        float4 x3 = ldcs4(hs + ((size_t)3*NTOK + t)*HDIM + h4);

        // ---- block reduce 10 values ----
        #pragma unroll
        for (int k = 0; k < 10; k++) {
            #pragma unroll
            for (int o = 16; o > 0; o >>= 1)
                p[k] += __shfl_xor_sync(0xffffffffu, p[k], o);
        }
        if (lane == 0) {
            #pragma unroll
            for (int k = 0; k < 10; k++) red[warp][k] = p[k];
        }
        __syncthreads();
        if (tid < 10) {
            float s = 0.f;
            #pragma unroll
            for (int wi = 0; wi < 16; wi++) s += red[wi][tid];
            fin[tid] = s;
        }
        __syncthreads();

        // ---- per-token coefficient math (redundant across threads) ----
        const float inv_h = 1.0f / (float)HDIM;
        float g0 = rsqrtf(fin[0] * inv_h + EPSV) * inv_h;
        float g1 = rsqrtf(fin[5] * inv_h + EPSV) * inv_h;
        float m0[4], cc[4];
        #pragma unroll
        for (int n = 0; n < 4; n++) m0[n] = tanh_fast(fin[1 + n] * g0);
        #pragma unroll
        for (int n = 0; n < 4; n++) {
            float mv = tanh_fast(fin[6 + n] * g1);
            if (n == 0) {
                cc[0] = 1.f + mv * __ldg(&cw[0*4]);
                cc[1] = 1.f + mv * __ldg(&cw[1*4]);
                cc[2] = 1.f + mv * __ldg(&cw[2*4]);
                cc[3] = 1.f + mv * __ldg(&cw[3*4]);
            } else {
                cc[0] = fmaf(mv, __ldg(&cw[0*4 + n]), cc[0]);
                cc[1] = fmaf(mv, __ldg(&cw[1*4 + n]), cc[1]);
                cc[2] = fmaf(mv, __ldg(&cw[2*4 + n]), cc[2]);
                cc[3] = fmaf(mv, __ldg(&cw[3*4 + n]), cc[3]);
            }
        }

        // ---- phase 2: elementwise combine ----
        float xc[4][4];
        xc[0][0]=x0.x; xc[0][1]=x0.y; xc[0][2]=x0.z; xc[0][3]=x0.w;
        xc[1][0]=x1.x; xc[1][1]=x1.y; xc[1][2]=x1.z; xc[1][3]=x1.w;
        xc[2][0]=x2.x; xc[2][1]=x2.y; xc[2][2]=x2.z; xc[2][3]=x2.w;
        xc[3][0]=x3.x; xc[3][1]=x3.y; xc[3][2]=x3.z; xc[3][3]=x3.w;
        const float ac[4] = {av.x, av.y, av.z, av.w};
        const float sc[4] = {sv.x, sv.y, sv.z, sv.w};

        float pr[4][4];   // pred[j][comp]
        #pragma unroll
        for (int j = 0; j < 4; j++) {
            float cr[4];
            #pragma unroll
            for (int i = 0; i < 4; i++) {
                float s = 0.f;
                #pragma unroll
                for (int n = 0; n < 4; n++) s += m0[n] * __ldg(&pw[(j*4 + i)*4 + n]);
                cr[i] = s;
            }
            #pragma unroll
            for (int comp = 0; comp < 4; comp++) {
                float s = xc[j][comp];
                #pragma unroll
                for (int i = 0; i < 4; i++) s = fmaf(cr[i], xc[i][comp], s);
                pr[j][comp] = s;
            }
        }

        #pragma unroll
        for (int n = 0; n < 4; n++) {
            float4 o4;
            float* op = &o4.x;
            #pragma unroll
            for (int comp = 0; comp < 4; comp++) {
                float innov = ac[comp] - pr[0][comp];
                op[comp] = (pr[n][comp] + innov * cc[n]) * sc[comp];
            }
            stcs4(out + ((size_t)n*NTOK + t)*HDIM + h4, o4);
        }
    }
}

extern "C" void kernel_launch(void* const* d_in, const int* in_sizes, int n_in,
                              void* d_out, int out_size)
{
    const float* hs     = (const float*)d_in[0];
    const float* act    = (const float*)d_in[1];
    const float* w      = (const float*)d_in[2];
    const float* rw     = (const float*)d_in[3];
    const float* pw     = (const float*)d_in[4];
    const float* cw     = (const float*)d_in[5];
    const float* oscale = (const float*)d_in[6];
    float* out = (float*)d_out;

    fuse_weights_kernel<<<(4*HDIM + 255)/256, 256>>>(w, rw);
    altup_persist_kernel<<<NCTAS, NTHREADS>>>(hs, act, pw, cw, oscale, out);
}

// round 10
// speedup vs baseline: 1.3557x; 1.1747x over previous
#include <cuda_runtime.h>
#include <cstdint>

#define HDIM 2048
#define NTOK 8192          // B*S
#define NTHREADS 512
#define NCTAS 456          // 152 SMs * 3 resident CTAs
#define EPSV 1e-6f

__device__ __forceinline__ float4 ldcs4(const float* p) {
    float4 v;
    asm volatile("ld.global.cs.v4.f32 {%0,%1,%2,%3}, [%4];"
                 : "=f"(v.x), "=f"(v.y), "=f"(v.z), "=f"(v.w) : "l"(p));
    return v;
}
__device__ __forceinline__ void stcs4(float* p, float4 v) {
    asm volatile("st.global.cs.v4.f32 [%0], {%1,%2,%3,%4};"
                 :: "l"(p), "f"(v.x), "f"(v.y), "f"(v.z), "f"(v.w));
}
__device__ __forceinline__ float tanh_fast(float x) {
    float y; asm("tanh.approx.f32 %0, %1;" : "=f"(y) : "f"(x)); return y;
}
__device__ __forceinline__ float dot4(float4 a, float4 b) {
    return a.x*b.x + a.y*b.y + a.z*b.z + a.w*b.w;
}

__global__ __launch_bounds__(NTHREADS, 3)
void altup_v6_kernel(const float* __restrict__ hs,     // [4, NTOK, H]
                     const float* __restrict__ act,    // [NTOK, H]
                     const float* __restrict__ w,      // [H]
                     const float* __restrict__ rw,     // [4, H]
                     const float* __restrict__ pw,     // [16, 4]
                     const float* __restrict__ cw,     // [4, 4]
                     const float* __restrict__ oscale, // [H]
                     float* __restrict__ out)          // [4, NTOK, H]
{
    const int tid = threadIdx.x;
    const int h4  = tid * 4;

    __shared__ float q_s[4][HDIM];     // fused router weights w*rw[n], 32KB
    __shared__ float pw_s[64];         // prediction_w
    __shared__ float cw_s[16];         // correction_w
    __shared__ float red[16][10];
    __shared__ float coef[20];         // c[16] then cc[4], per current token

    // ---- one-time staging: q = w * rw (4*2048 floats, 512 threads * 16) ----
    #pragma unroll
    for (int r = 0; r < 4; r++) {
        float4 wv = __ldg((const float4*)(w + h4));
        float4 rv = __ldg((const float4*)(rw + r*HDIM + h4));
        *(float4*)&q_s[r][h4] = make_float4(wv.x*rv.x, wv.y*rv.y, wv.z*rv.z, wv.w*rv.w);
    }
    if (tid < 64) pw_s[tid] = pw[tid];
    if (tid < 16) cw_s[tid] = cw[tid];
    const float4 sv = __ldg((const float4*)(oscale + h4));   // persistent in regs
    __syncthreads();

    const int warp = tid >> 5, lane = tid & 31;
    const float inv_h = 1.0f / (float)HDIM;

    for (int t = blockIdx.x; t < NTOK; t += NCTAS) {
        // ---- phase 1: reduction streams ----
        float4 x0 = ldcs4(hs  + (size_t)t * HDIM + h4);
        float4 av = ldcs4(act + (size_t)t * HDIM + h4);

        float p[10];
        {
            float4 q0 = *(const float4*)&q_s[0][h4];
            float4 q1 = *(const float4*)&q_s[1][h4];
            p[0] = dot4(x0, x0);
            p[1] = dot4(x0, q0);  p[2] = dot4(x0, q1);
            p[5] = dot4(av, av);
            p[6] = dot4(av, q0);  p[7] = dot4(av, q1);
        }
        {
            float4 q2 = *(const float4*)&q_s[2][h4];
            float4 q3 = *(const float4*)&q_s[3][h4];
            p[3] = dot4(x0, q2);  p[4] = dot4(x0, q3);
            p[8] = dot4(av, q2);  p[9] = dot4(av, q3);
        }

        // ---- prefetch phase-2 streams before the reduce ----
        float4 x1 = ldcs4(hs + ((size_t)1*NTOK + t)*HDIM + h4);
        float4 x2 = ldcs4(hs + ((size_t)2*NTOK + t)*HDIM + h4);
        float4 x3 = ldcs4(hs + ((size_t)3*NTOK + t)*HDIM + h4);

        // ---- block reduce: warp shuffle + smem ----
        #pragma unroll
        for (int k = 0; k < 10; k++) {
            #pragma unroll
            for (int o = 16; o > 0; o >>= 1)
                p[k] += __shfl_xor_sync(0xffffffffu, p[k], o);
        }
        if (lane == 0) {
            #pragma unroll
            for (int k = 0; k < 10; k++) red[warp][k] = p[k];
        }
        __syncthreads();

        // ---- warp 0 alone: finalize sums + ALL coefficient math ----
        if (warp == 0) {
            float f = 0.f;
            if (lane < 10) {
                #pragma unroll
                for (int wi = 0; wi < 16; wi++) f += red[wi][lane];
            }
            float fin[10];
            #pragma unroll
            for (int k = 0; k < 10; k++)
                fin[k] = __shfl_sync(0xffffffffu, f, k);

            float g0 = rsqrtf(fin[0] * inv_h + EPSV) * inv_h;
            float g1 = rsqrtf(fin[5] * inv_h + EPSV) * inv_h;

            if (lane < 16) {
                // c[j][i], j = lane>>2, i = lane&3
                float s = 0.f;
                #pragma unroll
                for (int n = 0; n < 4; n++)
                    s = fmaf(tanh_fast(fin[1 + n] * g0), pw_s[lane*4 + n], s);
                coef[lane] = s;
            } else if (lane < 20) {
                int n = lane - 16;
                float s = 1.0f;
                #pragma unroll
                for (int k = 0; k < 4; k++)
                    s = fmaf(tanh_fast(fin[6 + k] * g1), cw_s[n*4 + k], s);
                coef[16 + n] = s;
            }
        }
        __syncthreads();

        // ---- phase 2: elementwise combine (c/cc via LDS broadcast) ----
        float xc[4][4];
        xc[0][0]=x0.x; xc[0][1]=x0.y; xc[0][2]=x0.z; xc[0][3]=x0.w;
        xc[1][0]=x1.x; xc[1][1]=x1.y; xc[1][2]=x1.z; xc[1][3]=x1.w;
        xc[2][0]=x2.x; xc[2][1]=x2.y; xc[2][2]=x2.z; xc[2][3]=x2.w;
        xc[3][0]=x3.x; xc[3][1]=x3.y; xc[3][2]=x3.z; xc[3][3]=x3.w;
        const float ac[4] = {av.x, av.y, av.z, av.w};
        const float sc[4] = {sv.x, sv.y, sv.z, sv.w};

        // pred row 0 first (needed for innovation), then rows stream out
        float pr0[4];
        {
            const float c0 = coef[0], c1 = coef[1], c2 = coef[2], c3 = coef[3];
            #pragma unroll
            for (int comp = 0; comp < 4; comp++) {
                float s = xc[0][comp];
                s = fmaf(c0, xc[0][comp], s);
                s = fmaf(c1, xc[1][comp], s);
                s = fmaf(c2, xc[2][comp], s);
                s = fmaf(c3, xc[3][comp], s);
                pr0[comp] = s;
            }
        }
        float innov[4];
        #pragma unroll
        for (int comp = 0; comp < 4; comp++) innov[comp] = ac[comp] - pr0[comp];

        // row 0 output
        {
            const float cc0 = coef[16];
            float4 o4;
            o4.x = (pr0[0] + innov[0]*cc0) * sc[0];
            o4.y = (pr0[1] + innov[1]*cc0) * sc[1];
            o4.z = (pr0[2] + innov[2]*cc0) * sc[2];
            o4.w = (pr0[3] + innov[3]*cc0) * sc[3];
            stcs4(out + ((size_t)t)*HDIM + h4, o4);
        }
        // rows 1..3
        #pragma unroll
        for (int j = 1; j < 4; j++) {
            const float c0 = coef[j*4+0], c1 = coef[j*4+1],
                        c2 = coef[j*4+2], c3 = coef[j*4+3];
            const float ccj = coef[16 + j];
            float4 o4;
            float* op = &o4.x;
            #pragma unroll
            for (int comp = 0; comp < 4; comp++) {
                float s = xc[j][comp];
                s = fmaf(c0, xc[0][comp], s);
                s = fmaf(c1, xc[1][comp], s);
                s = fmaf(c2, xc[2][comp], s);
                s = fmaf(c3, xc[3][comp], s);
                op[comp] = (s + innov[comp]*ccj) * sc[comp];
            }
            stcs4(out + ((size_t)j*NTOK + t)*HDIM + h4, o4);
        }
        __syncthreads();   // protect red/coef reuse next iteration
    }
}

extern "C" void kernel_launch(void* const* d_in, const int* in_sizes, int n_in,
                              void* d_out, int out_size)
{
    const float* hs     = (const float*)d_in[0];
    const float* act    = (const float*)d_in[1];
    const float* w      = (const float*)d_in[2];
    const float* rw     = (const float*)d_in[3];
    const float* pw     = (const float*)d_in[4];
    const float* cw     = (const float*)d_in[5];
    const float* oscale = (const float*)d_in[6];
    float* out = (float*)d_out;

    altup_v6_kernel<<<NCTAS, NTHREADS>>>(hs, act, w, rw, pw, cw, oscale, out);
}